// round 4
// baseline (speedup 1.0000x reference)
#include <cuda_runtime.h>
#include <math.h>

#define Bn 32
#define Ln 32
#define NCc 528
#define Dd 384
#define MAXP 32768

// ---------------- device scratch (static, allocation-rule-safe) ----------------
__device__ float g_A [(size_t)Bn*NCc*Dd];   // cell @ W0   (inside) / parent @ out_W0 (outside)
__device__ float g_Bb[(size_t)Bn*NCc*Dd];   // cell @ W1   (inside) / sib @ out_W1   (outside)
__device__ float g_Cm[(size_t)Bn*NCc*Dd];   // cell @ bi   (inside) / sib @ out_bi   (outside)
__device__ float g_H [(size_t)MAXP*Dd];     // per-pair h
__device__ float g_X [(size_t)MAXP*Dd];     // per-pair xc
__device__ float g_P [MAXP];                // per-pair softmax weight

__host__ __device__ __forceinline__ int offi(int l){ return l*Ln - (l*(l-1))/2; }

__device__ __forceinline__ float sigma_h_f(float x){
    float s = 1.f/(1.f+expf(-x));
    return x * tanhf(sqrtf(s));
}

__device__ __forceinline__ void in_idx(int level,int pos,int n,int&li,int&ri){
    li = offi(n) + pos;
    ri = offi(level-n-1) + pos + n + 1;
}
__device__ __forceinline__ void out_idx(int level,int pos,int n,int&par,int&sib){
    int T1 = Ln - pos - level - 1;
    if (n < T1){ par = offi(level+n+1)+pos;     sib = offi(n)+pos+level+1; }
    else { int s = n - T1; par = offi(level+s+1)+pos-s-1; sib = offi(s)+pos-s-1; }
}

// 128-thread block reduce of (sum, sumsq)
__device__ __forceinline__ void blockReduce2_128(float& s, float& q){
    __shared__ float shm[8];
    #pragma unroll
    for (int o=16;o>0;o>>=1){
        s += __shfl_xor_sync(0xffffffffu, s, o);
        q += __shfl_xor_sync(0xffffffffu, q, o);
    }
    int w = threadIdx.x>>5;
    if ((threadIdx.x&31)==0){ shm[w]=s; shm[4+w]=q; }
    __syncthreads();
    s = shm[0]+shm[1]+shm[2]+shm[3];
    q = shm[4]+shm[5]+shm[6]+shm[7];
    __syncthreads();
}

// ---------------- generic 64x64-tile SGEMM (K=N=384), gathered rows ----------------
// row r -> global row g = (r/Ls)*bstride + cellOff + (r%Ls); dense: Ls=rows,bstride=0,cellOff=0
struct GM { const float* W[3]; float* C[3]; };

__global__ void __launch_bounds__(256) gemm_k(
    const float* __restrict__ Abase, GM gm, const float* __restrict__ bias,
    int rows, int Ls, int bstride, int cellOff, int epi)
{
    const float* __restrict__ W  = gm.W[blockIdx.z];
    float*       __restrict__ Cb = gm.C[blockIdx.z];
    __shared__ float As[16][64];
    __shared__ float Bs[16][64];
    int tid = threadIdx.x;
    int bm = blockIdx.x<<6, bn = blockIdx.y<<6;
    int tx = tid & 15, ty = tid >> 4;
    float acc[4][4];
    #pragma unroll
    for (int i=0;i<4;i++){
        #pragma unroll
        for (int j=0;j<4;j++) acc[i][j]=0.f;
    }
    int mload = tid>>2;
    int rA = bm + mload;
    int kA0 = (tid&3)<<2;
    const float* Ap = nullptr;
    if (rA < rows){
        int b = rA / Ls; int p = rA - b*Ls;
        Ap = Abase + (size_t)(b*bstride + cellOff + p)*Dd + kA0;
    }
    int kB = tid>>4; int nB = (tid&15)<<2;
    const float* Wp = W + (size_t)kB*Dd + bn + nB;
    for (int k0=0;k0<Dd;k0+=16){
        float4 av = Ap ? *(const float4*)(Ap + k0) : make_float4(0.f,0.f,0.f,0.f);
        float4 bv = *(const float4*)(Wp + (size_t)k0*Dd);
        As[kA0+0][mload]=av.x; As[kA0+1][mload]=av.y;
        As[kA0+2][mload]=av.z; As[kA0+3][mload]=av.w;
        *(float4*)&Bs[kB][nB] = bv;
        __syncthreads();
        #pragma unroll
        for (int kk=0;kk<16;kk++){
            float4 a4 = *(const float4*)&As[kk][ty<<2];
            float4 b4 = *(const float4*)&Bs[kk][tx<<2];
            acc[0][0]+=a4.x*b4.x; acc[0][1]+=a4.x*b4.y; acc[0][2]+=a4.x*b4.z; acc[0][3]+=a4.x*b4.w;
            acc[1][0]+=a4.y*b4.x; acc[1][1]+=a4.y*b4.y; acc[1][2]+=a4.y*b4.z; acc[1][3]+=a4.y*b4.w;
            acc[2][0]+=a4.z*b4.x; acc[2][1]+=a4.z*b4.y; acc[2][2]+=a4.z*b4.z; acc[2][3]+=a4.z*b4.w;
            acc[3][0]+=a4.w*b4.x; acc[3][1]+=a4.w*b4.y; acc[3][2]+=a4.w*b4.z; acc[3][3]+=a4.w*b4.w;
        }
        __syncthreads();
    }
    #pragma unroll
    for (int i=0;i<4;i++){
        int r = bm + (ty<<2) + i;
        if (r < rows){
            int b = r / Ls; int p = r - b*Ls;
            float* Crow = Cb + (size_t)(b*bstride + cellOff + p)*Dd + bn + (tx<<2);
            float4 v;
            v.x=acc[i][0]; v.y=acc[i][1]; v.z=acc[i][2]; v.w=acc[i][3];
            if (epi){
                int c = bn + (tx<<2);
                v.x = sigma_h_f(v.x + bias[c+0]);
                v.y = sigma_h_f(v.y + bias[c+1]);
                v.z = sigma_h_f(v.z + bias[c+2]);
                v.w = sigma_h_f(v.w + bias[c+3]);
            }
            *(float4*)Crow = v;
        }
    }
}

// ---------------- score + softmax kernels ----------------
__global__ void __launch_bounds__(256) score_in_k(
    const float* __restrict__ ih, float* __restrict__ isb,
    const float* __restrict__ cM, float* __restrict__ P, int level)
{
    int Ls = Ln - level;
    int bp = blockIdx.x;
    int b = bp / Ls, pos = bp - b*Ls;
    int warp = threadIdx.x >> 5, lane = threadIdx.x & 31;
    __shared__ float sc[32];
    for (int n = warp; n < level; n += 8){
        int li, ri; in_idx(level, pos, n, li, ri);
        const float* u = cM + (size_t)(b*NCc + li)*Dd;
        const float* v = ih + (size_t)(b*NCc + ri)*Dd;
        float s = 0.f;
        #pragma unroll 4
        for (int d = lane; d < Dd; d += 32) s += u[d]*v[d];
        #pragma unroll
        for (int o=16;o>0;o>>=1) s += __shfl_xor_sync(0xffffffffu, s, o);
        if (lane==0) sc[n] = s + isb[b*NCc+li] + isb[b*NCc+ri];
    }
    __syncthreads();
    if (warp==0){
        float v = (lane < level) ? sc[lane] : -1e30f;
        float m = v;
        #pragma unroll
        for (int o=16;o>0;o>>=1) m = fmaxf(m, __shfl_xor_sync(0xffffffffu, m, o));
        float e = (lane < level) ? expf(v - m) : 0.f;
        float se = e;
        #pragma unroll
        for (int o=16;o>0;o>>=1) se += __shfl_xor_sync(0xffffffffu, se, o);
        float p = e / se;
        float pb = (lane < level) ? p * v : 0.f;
        #pragma unroll
        for (int o=16;o>0;o>>=1) pb += __shfl_xor_sync(0xffffffffu, pb, o);
        if (lane < level) P[(size_t)bp*level + lane] = p;
        if (lane==0) isb[b*NCc + offi(level) + pos] = pb;
    }
}

__global__ void __launch_bounds__(256) score_out_k(
    const float* __restrict__ oh, float* __restrict__ osb,
    const float* __restrict__ isb, const float* __restrict__ cM,
    float* __restrict__ P, int level)
{
    int Ls = Ln - level, N = Ln - level - 1;
    int bp = blockIdx.x;
    int b = bp / Ls, pos = bp - b*Ls;
    int warp = threadIdx.x >> 5, lane = threadIdx.x & 31;
    __shared__ float sc[32];
    for (int n = warp; n < N; n += 8){
        int par, sib; out_idx(level, pos, n, par, sib);
        const float* u = cM + (size_t)(b*NCc + sib)*Dd;
        const float* v = oh + (size_t)(b*NCc + par)*Dd;
        float s = 0.f;
        #pragma unroll 4
        for (int d = lane; d < Dd; d += 32) s += u[d]*v[d];
        #pragma unroll
        for (int o=16;o>0;o>>=1) s += __shfl_xor_sync(0xffffffffu, s, o);
        if (lane==0) sc[n] = s + isb[b*NCc+sib] + osb[b*NCc+par];
    }
    __syncthreads();
    if (warp==0){
        float v = (lane < N) ? sc[lane] : -1e30f;
        float m = v;
        #pragma unroll
        for (int o=16;o>0;o>>=1) m = fmaxf(m, __shfl_xor_sync(0xffffffffu, m, o));
        float e = (lane < N) ? expf(v - m) : 0.f;
        float se = e;
        #pragma unroll
        for (int o=16;o>0;o>>=1) se += __shfl_xor_sync(0xffffffffu, se, o);
        float p = e / se;
        float pb = (lane < N) ? p * v : 0.f;
        #pragma unroll
        for (int o=16;o>0;o>>=1) pb += __shfl_xor_sync(0xffffffffu, pb, o);
        if (lane < N) P[(size_t)bp*N + lane] = p;
        if (lane==0) osb[b*NCc + offi(level) + pos] = pb;
    }
}

// ---------------- per-pair h = sigma_h(A[a] + B[b] + b0) ----------------
__global__ void __launch_bounds__(384) h_k(
    const float* __restrict__ Abuf, const float* __restrict__ Bbuf,
    const float* __restrict__ b0, float* __restrict__ H,
    int level, int nC, int Ls, int outside, int Pn)
{
    int pl = threadIdx.x / 96;
    int d  = threadIdx.x - pl*96;
    int pair = blockIdx.x*4 + pl;
    if (pair >= Pn) return;
    int bp = pair / nC, n = pair - bp*nC;
    int b = bp / Ls, pos = bp - b*Ls;
    int ia, ib;
    if (!outside) in_idx(level, pos, n, ia, ib);
    else          out_idx(level, pos, n, ia, ib);
    const float4* a  = (const float4*)(Abuf + (size_t)(b*NCc+ia)*Dd);
    const float4* bb = (const float4*)(Bbuf + (size_t)(b*NCc+ib)*Dd);
    const float4* bi = (const float4*)b0;
    float4 av = a[d], bv = bb[d], cv = bi[d];
    float4 h;
    h.x = sigma_h_f(av.x+bv.x+cv.x);
    h.y = sigma_h_f(av.y+bv.y+cv.y);
    h.z = sigma_h_f(av.z+bv.z+cv.z);
    h.w = sigma_h_f(av.w+bv.w+cv.w);
    ((float4*)(H + (size_t)pair*Dd))[d] = h;
}

// ---------------- p-weighted sum over candidates + layer_norm ----------------
__global__ void __launch_bounds__(128) reduceln_k(
    const float* __restrict__ XC, const float* __restrict__ P,
    const float* __restrict__ gamma, const float* __restrict__ beta,
    float* __restrict__ out, int nC, int Ls, int cellOff)
{
    int bp = blockIdx.x;
    int b = bp / Ls, pos = bp - b*Ls;
    int t = threadIdx.x;
    float a0=0.f, a1=0.f, a2=0.f;
    const float* xrow = XC + (size_t)bp*nC*Dd;
    for (int n=0;n<nC;n++){
        float p = P[(size_t)bp*nC + n];
        const float* x = xrow + (size_t)n*Dd;
        a0 += p*x[t]; a1 += p*x[t+128]; a2 += p*x[t+256];
    }
    float s = a0+a1+a2;
    float q = a0*a0+a1*a1+a2*a2;
    blockReduce2_128(s, q);
    float mu = s * (1.f/384.f);
    float var = q * (1.f/384.f) - mu*mu;
    float r = rsqrtf(var + 1e-5f);
    float* o = out + (size_t)(b*NCc + cellOff + pos)*Dd;
    o[t]     = (a0-mu)*r*gamma[t]     + beta[t];
    o[t+128] = (a1-mu)*r*gamma[t+128] + beta[t+128];
    o[t+256] = (a2-mu)*r*gamma[t+256] + beta[t+256];
}

// ---------------- leaf: sigma_h(pre + leaf_b) -> layer_norm -> ih; zero is_ ----------------
__global__ void __launch_bounds__(128) leaf_k(
    const float* __restrict__ pre, const float* __restrict__ lb,
    const float* __restrict__ gamma, const float* __restrict__ beta,
    float* __restrict__ ih, float* __restrict__ isb)
{
    int row = blockIdx.x;         // B*32
    int b = row >> 5, pos = row & 31;
    int t = threadIdx.x;
    const float* pr = pre + (size_t)row*Dd;
    float a0 = sigma_h_f(pr[t]     + lb[t]);
    float a1 = sigma_h_f(pr[t+128] + lb[t+128]);
    float a2 = sigma_h_f(pr[t+256] + lb[t+256]);
    float s = a0+a1+a2, q = a0*a0+a1*a1+a2*a2;
    blockReduce2_128(s, q);
    float mu = s * (1.f/384.f);
    float var = q * (1.f/384.f) - mu*mu;
    float r = rsqrtf(var + 1e-5f);
    float* o = ih + (size_t)(b*NCc + pos)*Dd;
    o[t]     = (a0-mu)*r*gamma[t]     + beta[t];
    o[t+128] = (a1-mu)*r*gamma[t+128] + beta[t+128];
    o[t+256] = (a2-mu)*r*gamma[t+256] + beta[t+256];
    if (t==0) isb[b*NCc + pos] = 0.f;
}

// ---------------- root: oh[:, -1] = layer_norm(root_h); os[:, -1] = 0 ----------------
__global__ void __launch_bounds__(128) root_k(
    const float* __restrict__ rh,
    const float* __restrict__ gamma, const float* __restrict__ beta,
    float* __restrict__ oh, float* __restrict__ osb)
{
    int b = blockIdx.x;
    int t = threadIdx.x;
    float a0 = rh[t], a1 = rh[t+128], a2 = rh[t+256];
    float s = a0+a1+a2, q = a0*a0+a1*a1+a2*a2;
    blockReduce2_128(s, q);
    float mu = s * (1.f/384.f);
    float var = q * (1.f/384.f) - mu*mu;
    float r = rsqrtf(var + 1e-5f);
    float* o = oh + (size_t)(b*NCc + NCc-1)*Dd;
    o[t]     = (a0-mu)*r*gamma[t]     + beta[t];
    o[t+128] = (a1-mu)*r*gamma[t+128] + beta[t+128];
    o[t+256] = (a2-mu)*r*gamma[t+256] + beta[t+256];
    if (t==0) osb[b*NCc + NCc-1] = 0.f;
}

// ---------------- orchestration ----------------
extern "C" void kernel_launch(void* const* d_in, const int* in_sizes, int n_in,
                              void* d_out, int out_size)
{
    (void)in_sizes; (void)n_in; (void)out_size;
    const float* x        = (const float*)d_in[0];
    const float* leaf_W   = (const float*)d_in[1];
    const float* leaf_b   = (const float*)d_in[2];
    const float* in_ln_g  = (const float*)d_in[3];
    const float* in_ln_b  = (const float*)d_in[4];
    const float* out_ln_g = (const float*)d_in[5];
    const float* out_ln_b = (const float*)d_in[6];
    const float* root_h   = (const float*)d_in[7];
    const float* in_bi    = (const float*)d_in[8];
    const float* out_bi   = (const float*)d_in[9];
    const float* in_W0    = (const float*)d_in[10];
    const float* in_W1    = (const float*)d_in[11];
    const float* in_B0    = (const float*)d_in[12];
    const float* in_W2    = (const float*)d_in[13];
    const float* in_B1    = (const float*)d_in[14];
    const float* out_W0   = (const float*)d_in[15];
    const float* out_W1   = (const float*)d_in[16];
    const float* out_B0   = (const float*)d_in[17];
    const float* out_W2   = (const float*)d_in[18];
    const float* out_B1   = (const float*)d_in[19];

    float* ih  = (float*)d_out;
    float* isb = ih  + (size_t)Bn*NCc*Dd;
    float* oh  = isb + (size_t)Bn*NCc;
    float* osb = oh  + (size_t)Bn*NCc*Dd;

    float *A,*Bb,*Cm,*H,*X,*P;
    cudaGetSymbolAddress((void**)&A,  g_A);
    cudaGetSymbolAddress((void**)&Bb, g_Bb);
    cudaGetSymbolAddress((void**)&Cm, g_Cm);
    cudaGetSymbolAddress((void**)&H,  g_H);
    cudaGetSymbolAddress((void**)&X,  g_X);
    cudaGetSymbolAddress((void**)&P,  g_P);

    // ---- leaf level ----
    {
        GM gm; gm.W[0]=leaf_W; gm.C[0]=H; gm.W[1]=gm.W[2]=nullptr; gm.C[1]=gm.C[2]=nullptr;
        gemm_k<<<dim3(16,6,1),256>>>(x, gm, nullptr, Bn*Ln, Bn*Ln, 0, 0, 0);
        leaf_k<<<Bn*Ln,128>>>(H, leaf_b, in_ln_g, in_ln_b, ih, isb);
        GM g3; g3.W[0]=in_W0; g3.W[1]=in_W1; g3.W[2]=in_bi;
        g3.C[0]=A; g3.C[1]=Bb; g3.C[2]=Cm;
        gemm_k<<<dim3(16,6,3),256>>>(ih, g3, nullptr, Bn*Ln, Ln, NCc, 0, 0);
    }

    // ---- inside pass ----
    for (int level=1; level<Ln; level++){
        int Ls = Ln-level, nC = level;
        int rowsBP = Bn*Ls, Pn = rowsBP*nC;
        score_in_k<<<rowsBP,256>>>(ih, isb, Cm, P, level);
        h_k<<<(Pn+3)/4,384>>>(A, Bb, in_B0, H, level, nC, Ls, 0, Pn);
        GM g1; g1.W[0]=in_W2; g1.C[0]=X; g1.W[1]=g1.W[2]=nullptr; g1.C[1]=g1.C[2]=nullptr;
        gemm_k<<<dim3((Pn+63)/64,6,1),256>>>(H, g1, in_B1, Pn, Pn, 0, 0, 1);
        reduceln_k<<<rowsBP,128>>>(X, P, in_ln_g, in_ln_b, ih, nC, Ls, offi(level));
        if (level < Ln-1){
            GM g3; g3.W[0]=in_W0; g3.W[1]=in_W1; g3.W[2]=in_bi;
            g3.C[0]=A; g3.C[1]=Bb; g3.C[2]=Cm;
            gemm_k<<<dim3((rowsBP+63)/64,6,3),256>>>(ih, g3, nullptr, rowsBP, Ls, NCc, offi(level), 0);
        }
    }

    // ---- outside prep: precompute sib @ out_W1, sib @ out_bi for ALL inside cells ----
    {
        GM g2; g2.W[0]=out_W1; g2.W[1]=out_bi; g2.C[0]=Bb; g2.C[1]=Cm;
        g2.W[2]=nullptr; g2.C[2]=nullptr;
        gemm_k<<<dim3((Bn*NCc+63)/64,6,2),256>>>(ih, g2, nullptr, Bn*NCc, NCc, NCc, 0, 0);
        root_k<<<Bn,128>>>(root_h, out_ln_g, out_ln_b, oh, osb);
        GM gr; gr.W[0]=out_W0; gr.C[0]=A; gr.W[1]=gr.W[2]=nullptr; gr.C[1]=gr.C[2]=nullptr;
        gemm_k<<<dim3(1,6,1),256>>>(oh, gr, nullptr, Bn, 1, NCc, NCc-1, 0);
    }

    // ---- outside pass ----
    for (int level=Ln-2; level>=0; level--){
        int Ls = Ln-level, nC = Ln-level-1;
        int rowsBP = Bn*Ls, Pn = rowsBP*nC;
        score_out_k<<<rowsBP,256>>>(oh, osb, isb, Cm, P, level);
        h_k<<<(Pn+3)/4,384>>>(A, Bb, out_B0, H, level, nC, Ls, 1, Pn);
        GM g1; g1.W[0]=out_W2; g1.C[0]=X; g1.W[1]=g1.W[2]=nullptr; g1.C[1]=g1.C[2]=nullptr;
        gemm_k<<<dim3((Pn+63)/64,6,1),256>>>(H, g1, out_B1, Pn, Pn, 0, 0, 1);
        reduceln_k<<<rowsBP,128>>>(X, P, out_ln_g, out_ln_b, oh, nC, Ls, offi(level));
        if (level > 0){
            GM g3; g3.W[0]=out_W0; g3.C[0]=A; g3.W[1]=g3.W[2]=nullptr; g3.C[1]=g3.C[2]=nullptr;
            gemm_k<<<dim3((rowsBP+63)/64,6,1),256>>>(oh, g3, nullptr, rowsBP, Ls, NCc, offi(level), 0);
        }
    }
}